// round 8
// baseline (speedup 1.0000x reference)
#include <cuda_runtime.h>
#include <cuda_bf16.h>
#include <cstdint>

#define VOCAB 30000
#define TT    512
#define BATCH 4096
#define HH    100
#define EE    32
#define BB    32       // batch per CTA
#define NBLK  128      // BATCH / BB
#define NTH   800      // 25 warps; thread = (bg 0..7, j 0..99), 4 batches each
#define HTP   68       // padded htd row: 32 b * 2 (dup) + 4 pad floats
#define HTSZ  (HH * HTP)   // 6800 floats per buffer

// 48 MB table: xpre[v][j][gate] = bias_g[j] + emb[v]·Wg[0:32, j]; gate order f,i,o,g
__device__ float g_xpre[(size_t)VOCAB * HH * 4];

typedef unsigned long long u64;

__device__ __forceinline__ float fsigm(float z) {
    return __fdividef(1.f, 1.f + __expf(-z));
}
__device__ __forceinline__ float ftanh(float z) {
    return 1.f - __fdividef(2.f, __expf(2.f * z) + 1.f);
}
__device__ __forceinline__ void ffma2(u64& d, u64 a, u64 b) {
    asm("fma.rn.f32x2 %0, %1, %2, %0;" : "+l"(d) : "l"(a), "l"(b));
}
__device__ __forceinline__ u64 fadd2(u64 a, u64 b) {
    u64 r; asm("add.rn.f32x2 %0, %1, %2;" : "=l"(r) : "l"(a), "l"(b)); return r;
}
__device__ __forceinline__ u64 mk2(float lo, float hi) {
    u64 r; asm("mov.b64 %0, {%1, %2};" : "=l"(r) : "f"(lo), "f"(hi)); return r;
}
__device__ __forceinline__ float2 unpack2(u64 v) {
    float2 f; asm("mov.b64 {%0, %1}, %2;" : "=f"(f.x), "=f"(f.y) : "l"(v)); return f;
}

// ---------------------------------------------------------------------------
// Kernel 1: xpre[v][j][4] = bias + emb[v](1x32) · W[0:32]  (gate-interleaved)
// ---------------------------------------------------------------------------
__global__ void xpre_kernel(const float* __restrict__ emb,
                            const float* __restrict__ Wf, const float* __restrict__ bf,
                            const float* __restrict__ Wi, const float* __restrict__ bi,
                            const float* __restrict__ Wo, const float* __restrict__ bo,
                            const float* __restrict__ Wc, const float* __restrict__ bc) {
    int v = blockIdx.x;
    __shared__ float e[EE];
    if (threadIdx.x < EE) e[threadIdx.x] = emb[v * EE + threadIdx.x];
    __syncthreads();
    for (int n = threadIdx.x; n < HH * 4; n += blockDim.x) {
        int j = n >> 2, gate = n & 3;
        const float* W = (gate == 0) ? Wf : (gate == 1) ? Wi : (gate == 2) ? Wo : Wc;
        const float* b = (gate == 0) ? bf : (gate == 1) ? bi : (gate == 2) ? bo : bc;
        float s = b[j];
#pragma unroll
        for (int k = 0; k < EE; k++) s = fmaf(e[k], W[k * HH + j], s);
        g_xpre[((size_t)v * HH + j) * 4 + gate] = s;
    }
}

// ---------------------------------------------------------------------------
// Kernel 2: persistent fused LSTM. One CTA = 32 batch elems, 511 steps.
// 800 threads: (bg = tid/100) owns batches bg*4..bg*4+3, (j = tid%100) the
// output index (all 4 gates). W smem layout [k][j][4g] -> one LDS.128 gives
// both f32x2 operand pairs {f,i},{o,g} with no repacking. h stored duplicated
// ([k][b*2]) so broadcast LDS.128 yields pre-paired multipliers.
// ---------------------------------------------------------------------------
__global__ void __launch_bounds__(NTH, 1)
lstm_kernel(const int* __restrict__ data32,
            const float* __restrict__ Wf, const float* __restrict__ Wi,
            const float* __restrict__ Wo4, const float* __restrict__ Wc,
            const float* __restrict__ WoOut, const float* __restrict__ boOut,
            float* __restrict__ out) {
    extern __shared__ float smem[];
    float* Ws  = smem;                       // [100k][100j][4g]
    float* htd = smem + 40000;               // [2][100k][68] (b*2 duplicated)
    int*   itk = (int*)(smem + 40000 + 2 * HTSZ);
    int*   toks = itk;                       // [2][32]
    int*   ltok = itk + 2 * BB;              // [32]
    int*   flag = itk + 3 * BB;              // [1]

    const int tid = threadIdx.x;
    const int b0  = blockIdx.x * BB;

    if (tid == 0) {
        int is64 = 1;
        for (int i = 0; i < 64; i++)
            if (data32[2 * i + 1] != 0) { is64 = 0; break; }
        flag[0] = is64;
    }
    // stage W rows 32..131: Ws[(k*100+j)*4+g] = Wg[(32+k)*100 + j]
    for (int idx = tid; idx < HH * HH * 4; idx += NTH) {
        int g = idx & 3, kj = idx >> 2, k = kj / HH, j = kj % HH;
        const float* W = (g == 0) ? Wf : (g == 1) ? Wi : (g == 2) ? Wo4 : Wc;
        Ws[idx] = W[(EE + k) * HH + j];
    }
    for (int idx = tid; idx < HTSZ; idx += NTH) htd[idx] = 0.f;   // buffer 0 only
    __syncthreads();

    const int is64 = flag[0];
    if (tid < BB) {
        long long base = (long long)(b0 + tid) * TT;
        ltok[tid] = is64 ? data32[2 * (base + TT - 1)] : data32[base + TT - 1];
        toks[tid] = is64 ? data32[2 * base]            : data32[base];
    }
    __syncthreads();

    const int bg = tid / 100;   // 0..7, owns batches bg*4..bg*4+3
    const int j  = tid % 100;   // output index (all 4 gates)

    float c[4], hreg[4];
#pragma unroll
    for (int i = 0; i < 4; i++) { c[i] = 0.f; hreg[i] = 0.f; }

    int cur = 0;
    for (int t = 0; t < TT - 1; ++t) {
        if (tid < BB) {
            long long base = (long long)(b0 + tid) * TT + (t + 1);
            toks[(cur ^ 1) * BB + tid] = is64 ? data32[2 * base] : data32[base];
        }

        {
            // gather x-part preacts early (consumed in epilogue)
            int tk[4];
            u64 xfi[4], xog[4];
#pragma unroll
            for (int i = 0; i < 4; i++) {
                tk[i] = toks[cur * BB + bg * 4 + i];
                ulonglong2 xp = __ldg((const ulonglong2*)(g_xpre + ((size_t)tk[i] * HH + j) * 4));
                xfi[i] = xp.x;
                xog[i] = xp.y;
            }
            u64 afi[4], aog[4];
#pragma unroll
            for (int i = 0; i < 4; i++) { afi[i] = 0ull; aog[i] = 0ull; }

            const float* Wb = Ws + j * 4;                 // +k*400
            const float* Hb = htd + cur * HTSZ + bg * 8;  // +k*HTP
#pragma unroll 2
            for (int k = 0; k < HH; k += 2) {
                // W pairs come straight from LDS.128 (no MOV repack)
                ulonglong2 w0 = *(const ulonglong2*)(Wb + (size_t)k * 400);
                ulonglong2 w1 = *(const ulonglong2*)(Wb + (size_t)k * 400 + 400);
                ulonglong2 h00 = *(const ulonglong2*)(Hb + k * HTP);
                ulonglong2 h01 = *(const ulonglong2*)(Hb + k * HTP + 4);
                ulonglong2 h10 = *(const ulonglong2*)(Hb + k * HTP + HTP);
                ulonglong2 h11 = *(const ulonglong2*)(Hb + k * HTP + HTP + 4);
                ffma2(afi[0], h00.x, w0.x); ffma2(aog[0], h00.x, w0.y);
                ffma2(afi[1], h00.y, w0.x); ffma2(aog[1], h00.y, w0.y);
                ffma2(afi[2], h01.x, w0.x); ffma2(aog[2], h01.x, w0.y);
                ffma2(afi[3], h01.y, w0.x); ffma2(aog[3], h01.y, w0.y);
                ffma2(afi[0], h10.x, w1.x); ffma2(aog[0], h10.x, w1.y);
                ffma2(afi[1], h10.y, w1.x); ffma2(aog[1], h10.y, w1.y);
                ffma2(afi[2], h11.x, w1.x); ffma2(aog[2], h11.x, w1.y);
                ffma2(afi[3], h11.y, w1.x); ffma2(aog[3], h11.y, w1.y);
            }

            // epilogue: activate, masked c/h update, write duplicated h
            float* Hn = htd + (cur ^ 1) * HTSZ + j * HTP + bg * 8;
#pragma unroll
            for (int i = 0; i < 4; i++) {
                float2 zfi = unpack2(fadd2(afi[i], xfi[i]));
                float2 zog = unpack2(fadd2(aog[i], xog[i]));
                float f  = fsigm(zfi.x);
                float ii = fsigm(zfi.y);
                float o  = fsigm(zog.x);
                float g  = ftanh(zog.y);
                float cn = fmaf(c[i], f, ii * g);
                bool  m  = (tk[i] != ltok[bg * 4 + i]);
                float cv = m ? cn : c[i];
                float hv = m ? o * ftanh(cn) : hreg[i];
                c[i] = cv; hreg[i] = hv;
                *(u64*)(Hn + i * 2) = mk2(hv, hv);
            }
        }
        cur ^= 1;
        __syncthreads();
    }

    // output head: out[b] = sigmoid(h·Wo + bo); final h in htd[cur]
    if (tid < BB) {
        const float* Hf = htd + cur * HTSZ + tid * 2;
        float z = boOut[0];
#pragma unroll 4
        for (int k = 0; k < HH; k++) z = fmaf(Hf[k * HTP], WoOut[k], z);
        out[b0 + tid] = fsigm(z);
    }
}

// ---------------------------------------------------------------------------
extern "C" void kernel_launch(void* const* d_in, const int* in_sizes, int n_in,
                              void* d_out, int out_size) {
    const int*   data = (const int*)  d_in[0];   // int64 or int32 tokens (auto-detected)
    const float* emb  = (const float*)d_in[1];
    const float* Wfh  = (const float*)d_in[2];
    const float* bfh  = (const float*)d_in[3];
    const float* Wih  = (const float*)d_in[4];
    const float* bih  = (const float*)d_in[5];
    const float* Woh  = (const float*)d_in[6];
    const float* boh  = (const float*)d_in[7];
    const float* Wch  = (const float*)d_in[8];
    const float* bch  = (const float*)d_in[9];
    const float* Wo   = (const float*)d_in[10];
    const float* bo   = (const float*)d_in[11];
    float* out = (float*)d_out;

    xpre_kernel<<<VOCAB, 128>>>(emb, Wfh, bfh, Wih, bih, Woh, boh, Wch, bch);

    const size_t smem_bytes = (size_t)(40000 + 2 * HTSZ + 128) * 4;
    cudaFuncSetAttribute(lstm_kernel, cudaFuncAttributeMaxDynamicSharedMemorySize,
                         (int)smem_bytes);
    lstm_kernel<<<NBLK, NTH, smem_bytes>>>(data, Wfh, Wih, Woh, Wch, Wo, bo, out);
}

// round 10
// speedup vs baseline: 1.6881x; 1.6881x over previous
#include <cuda_runtime.h>
#include <cuda_fp16.h>
#include <cstdint>

#define VOCAB 30000
#define TT    512
#define HH    100
#define EE    32
#define BB    32
#define NBLK  128
#define NTH   416

// ---- SMEM byte offsets ----
#define SM_TOKS 0        // [2][32] int
#define SM_LTOK 256      // [32] int
#define SM_FLAG 384
#define SM_W    512      // 400 rows x 240 B fp16 (W^T, k-major, padded)
#define SM_AH   96512    // 32 rows x 240 B fp16 (h hi)
#define SM_AL   104192   // 32 rows x 240 B fp16 (h lo)
#define SM_GS   111872   // 32 x 404 f32 staging
#define SM_END  163584
#define GSTR    404      // gs row stride (floats); r*20 mod 32 distinct -> no STS conflicts

__device__ float g_xpre[(size_t)VOCAB * HH * 4];   // [v][j][f,i,o,g], exact fp32 x-part

__device__ __forceinline__ float fsigm(float z){ return __fdividef(1.f, 1.f + __expf(-z)); }
__device__ __forceinline__ float ftanh(float z){ return 1.f - __fdividef(2.f, __expf(2.f*z) + 1.f); }
__device__ __forceinline__ uint32_t smem_u32(const void* p){
    uint32_t a; asm("{ .reg .u64 t; cvta.to.shared.u64 t, %1; cvt.u32.u64 %0, t; }" : "=r"(a) : "l"(p)); return a;
}
__device__ __forceinline__ void ldsm_x4(uint32_t& r0, uint32_t& r1, uint32_t& r2, uint32_t& r3, uint32_t a){
    asm volatile("ldmatrix.sync.aligned.m8n8.x4.shared.b16 {%0,%1,%2,%3}, [%4];"
                 : "=r"(r0), "=r"(r1), "=r"(r2), "=r"(r3) : "r"(a));
}
__device__ __forceinline__ void ldsm_x2(uint32_t& r0, uint32_t& r1, uint32_t a){
    asm volatile("ldmatrix.sync.aligned.m8n8.x2.shared.b16 {%0,%1}, [%2];"
                 : "=r"(r0), "=r"(r1) : "r"(a));
}
__device__ __forceinline__ void mma16816(float* c, uint32_t a0, uint32_t a1, uint32_t a2, uint32_t a3,
                                         uint32_t b0, uint32_t b1){
    asm volatile("mma.sync.aligned.m16n8k16.row.col.f32.f16.f16.f32 "
                 "{%0,%1,%2,%3}, {%4,%5,%6,%7}, {%8,%9}, {%0,%1,%2,%3};"
                 : "+f"(c[0]), "+f"(c[1]), "+f"(c[2]), "+f"(c[3])
                 : "r"(a0), "r"(a1), "r"(a2), "r"(a3), "r"(b0), "r"(b1));
}

// ---------------------------------------------------------------------------
__global__ void xpre_kernel(const float* __restrict__ emb,
                            const float* __restrict__ Wf, const float* __restrict__ bf,
                            const float* __restrict__ Wi, const float* __restrict__ bi,
                            const float* __restrict__ Wo, const float* __restrict__ bo,
                            const float* __restrict__ Wc, const float* __restrict__ bc) {
    int v = blockIdx.x;
    __shared__ float e[EE];
    if (threadIdx.x < EE) e[threadIdx.x] = emb[v * EE + threadIdx.x];
    __syncthreads();
    for (int n = threadIdx.x; n < HH * 4; n += blockDim.x) {
        int j = n >> 2, gate = n & 3;
        const float* W = (gate==0)?Wf:(gate==1)?Wi:(gate==2)?Wo:Wc;
        const float* b = (gate==0)?bf:(gate==1)?bi:(gate==2)?bo:bc;
        float s = b[j];
#pragma unroll
        for (int k = 0; k < EE; k++) s = fmaf(e[k], W[k*HH+j], s);
        g_xpre[((size_t)v*HH + j)*4 + gate] = s;
    }
}

// ---------------------------------------------------------------------------
// Persistent HMMA LSTM: CTA = 32 batches, 511 steps.
// Per step: warps 0-9 do D[32,400] = [h_hi|h_lo](fp16) @ W^T(fp16) via
// mma.sync.m16n8k16 (fp32 accum), stage to gs; 400 threads do exact-fp32
// x-part add + activations + masked c/h update; h re-split hi/lo each step.
// ---------------------------------------------------------------------------
__global__ void __launch_bounds__(NTH, 1)
lstm_kernel(const int* __restrict__ data32,
            const float* __restrict__ Wf, const float* __restrict__ Wi,
            const float* __restrict__ Wo4, const float* __restrict__ Wc,
            const float* __restrict__ WoOut, const float* __restrict__ boOut,
            float* __restrict__ out) {
    extern __shared__ char smem[];
    const uint32_t sbase = smem_u32(smem);
    const int tid = threadIdx.x, wid = tid >> 5, lane = tid & 31;
    const int b0 = blockIdx.x * BB;

    int*   toks = (int*)(smem + SM_TOKS);
    int*   ltok = (int*)(smem + SM_LTOK);
    int*   flag = (int*)(smem + SM_FLAG);
    float* gs   = (float*)(smem + SM_GS);

    if (tid == 0) {
        int is64 = 1;
        for (int i = 0; i < 64; i++) if (data32[2*i+1] != 0) { is64 = 0; break; }
        flag[0] = is64;
    }
    // zero W + A staging (covers k-padding and h=0 init)
    for (int idx = tid*4; idx < SM_GS - SM_W; idx += NTH*4)
        *(uint32_t*)(smem + SM_W + idx) = 0u;
    __syncthreads();
    // fill W^T fp16: row n = gate*100+j, col k -> Wg[(32+k)*100+j]
    for (int idx = tid; idx < 400 * HH; idx += NTH) {
        int n = idx / HH, k = idx % HH, gate = n / HH, j = n % HH;
        const float* W = (gate==0)?Wf:(gate==1)?Wi:(gate==2)?Wo4:Wc;
        *(__half*)(smem + SM_W + n*240 + k*2) = __float2half_rn(W[(EE+k)*HH + j]);
    }
    const int is64 = flag[0];
    if (tid < BB) {
        long long base = (long long)(b0 + tid) * TT;
        ltok[tid] = is64 ? data32[2*(base+TT-1)] : data32[base+TT-1];
        toks[tid] = is64 ? data32[2*base]        : data32[base];
    }
    __syncthreads();

    const int bg = (tid < 400) ? tid / 100 : 0;   // 0..3: batches bg*8..bg*8+7
    const int j  = (tid < 400) ? tid % 100 : 0;
    float c[8], hreg[8];
#pragma unroll
    for (int i = 0; i < 8; i++) { c[i] = 0.f; hreg[i] = 0.f; }

    // mma-warp constants
    const int m0  = (wid < 5) ? 0 : 16;
    const int nt0 = (wid % 5) * 10;
    const uint32_t aOff = (uint32_t)(m0 + (lane & 15)) * 240u + (uint32_t)(lane >> 4) * 16u;
    const uint32_t bAdr = sbase + SM_W + (uint32_t)(nt0*8 + (lane & 7)) * 240u
                        + (uint32_t)((lane >> 3) & 1) * 16u;

    int cur = 0;
    for (int t = 0; t < TT - 1; ++t) {
        // B1: A staging (h hi/lo) + toks[cur] ready
        __syncthreads();

        int tk[8]; float4 xp[8];
        if (tid < 400) {
#pragma unroll
            for (int i = 0; i < 8; i++) {
                tk[i] = toks[cur * BB + bg*8 + i];
                xp[i] = __ldg((const float4*)(g_xpre + ((size_t)tk[i]*HH + j)*4));
            }
        }
        if (wid == 12 && lane < BB) {   // prefetch next tokens
            long long base = (long long)(b0 + lane) * TT + (t + 1);
            toks[(cur ^ 1) * BB + lane] = is64 ? data32[2*base] : data32[base];
        }

        if (wid < 10) {
            float acc[10][4];
#pragma unroll
            for (int i = 0; i < 10; i++) { acc[i][0]=0.f; acc[i][1]=0.f; acc[i][2]=0.f; acc[i][3]=0.f; }
#pragma unroll
            for (int term = 0; term < 2; term++) {
                uint32_t aBase = sbase + (term ? SM_AL : SM_AH) + aOff;
#pragma unroll
                for (int kc = 0; kc < 7; kc++) {
                    uint32_t a0,a1,a2,a3;
                    ldsm_x4(a0,a1,a2,a3, aBase + kc*32);
#pragma unroll
                    for (int i = 0; i < 10; i++) {
                        uint32_t b0r,b1r;
                        ldsm_x2(b0r,b1r, bAdr + i*(8*240) + kc*32);
                        mma16816(acc[i], a0,a1,a2,a3, b0r,b1r);
                    }
                }
            }
            int r0 = m0 + (lane >> 2), cl = (lane & 3) * 2;
#pragma unroll
            for (int i = 0; i < 10; i++) {
                int n = (nt0 + i)*8 + cl;
                *(float2*)(gs + r0*GSTR + n)     = make_float2(acc[i][0], acc[i][1]);
                *(float2*)(gs + (r0+8)*GSTR + n) = make_float2(acc[i][2], acc[i][3]);
            }
        }
        // B2: gs ready
        __syncthreads();

        if (tid < 400) {
#pragma unroll
            for (int i = 0; i < 8; i++) {
                int b = bg*8 + i;
                float f  = fsigm(gs[b*GSTR +       j] + xp[i].x);
                float ii = fsigm(gs[b*GSTR + 100 + j] + xp[i].y);
                float o  = fsigm(gs[b*GSTR + 200 + j] + xp[i].z);
                float gg = ftanh(gs[b*GSTR + 300 + j] + xp[i].w);
                float cn = fmaf(c[i], f, ii * gg);
                bool  m  = (tk[i] != ltok[b]);
                c[i]    = m ? cn : c[i];
                hreg[i] = m ? o * ftanh(cn) : hreg[i];
                __half hi = __float2half_rn(hreg[i]);
                __half lo = __float2half_rn(hreg[i] - __half2float(hi));
                *(__half*)(smem + SM_AH + b*240 + j*2) = hi;
                *(__half*)(smem + SM_AL + b*240 + j*2) = lo;
            }
        }
        cur ^= 1;
    }

    // output head
    __syncthreads();
    if (tid < 400) {
#pragma unroll
        for (int i = 0; i < 8; i++) gs[(bg*8 + i)*104 + j] = hreg[i];
    }
    __syncthreads();
    if (tid < BB) {
        float z = boOut[0];
#pragma unroll 4
        for (int k = 0; k < HH; k++) z = fmaf(gs[tid*104 + k], WoOut[k], z);
        out[b0 + tid] = fsigm(z);
    }
}

// ---------------------------------------------------------------------------
extern "C" void kernel_launch(void* const* d_in, const int* in_sizes, int n_in,
                              void* d_out, int out_size) {
    const int*   data = (const int*)  d_in[0];
    const float* emb  = (const float*)d_in[1];
    const float* Wfh  = (const float*)d_in[2];
    const float* bfh  = (const float*)d_in[3];
    const float* Wih  = (const float*)d_in[4];
    const float* bih  = (const float*)d_in[5];
    const float* Woh  = (const float*)d_in[6];
    const float* boh  = (const float*)d_in[7];
    const float* Wch  = (const float*)d_in[8];
    const float* bch  = (const float*)d_in[9];
    const float* Wo   = (const float*)d_in[10];
    const float* bo   = (const float*)d_in[11];
    float* out = (float*)d_out;

    xpre_kernel<<<VOCAB, 128>>>(emb, Wfh, bfh, Wih, bih, Woh, boh, Wch, bch);

    cudaFuncSetAttribute(lstm_kernel, cudaFuncAttributeMaxDynamicSharedMemorySize, SM_END);
    lstm_kernel<<<NBLK, NTH, SM_END>>>(data, Wfh, Wih, Woh, Wch, Wo, bo, out);
}

// round 12
// speedup vs baseline: 3.3108x; 1.9612x over previous
#include <cuda_runtime.h>
#include <cuda_fp16.h>
#include <cstdint>

#define VOCAB 30000
#define TT    512
#define HH    100
#define EE    32
#define BB    32
#define NBLK  128
#define NTH   416

// ---- SMEM byte offsets ----
#define SM_TOKS 0        // [2][32] int
#define SM_LTOK 256      // [32] int
#define SM_FLAG 384
#define SM_W    512      // 400 rows x 240 B fp16 (W^T, k-major, padded)
#define SM_AH   96512    // 32 rows x 240 B fp16 (h hi)
#define SM_AL   104192   // 32 rows x 240 B fp16 (h lo)
#define SM_GS   111872   // 32 x 404 f32 staging
#define SM_END  163584
#define GSTR    404      // gs row stride (floats)

__device__ float g_xpre[(size_t)VOCAB * HH * 4];   // [v][j][f,i,o,g], exact fp32 x-part

// exact (used for xpre build + final output only)
__device__ __forceinline__ float fsigm_x(float z){ return __fdividef(1.f, 1.f + __expf(-z)); }
// HW tanh path (epilogue)
__device__ __forceinline__ float ftanh_hw(float z){
    float r; asm("tanh.approx.f32 %0, %1;" : "=f"(r) : "f"(z)); return r;
}
__device__ __forceinline__ float fsigm_hw(float z){
    return fmaf(ftanh_hw(0.5f * z), 0.5f, 0.5f);
}
__device__ __forceinline__ uint32_t smem_u32(const void* p){
    uint32_t a; asm("{ .reg .u64 t; cvta.to.shared.u64 t, %1; cvt.u32.u64 %0, t; }" : "=r"(a) : "l"(p)); return a;
}
__device__ __forceinline__ void ldsm_x4(uint32_t& r0, uint32_t& r1, uint32_t& r2, uint32_t& r3, uint32_t a){
    asm volatile("ldmatrix.sync.aligned.m8n8.x4.shared.b16 {%0,%1,%2,%3}, [%4];"
                 : "=r"(r0), "=r"(r1), "=r"(r2), "=r"(r3) : "r"(a));
}
__device__ __forceinline__ void ldsm_x2(uint32_t& r0, uint32_t& r1, uint32_t a){
    asm volatile("ldmatrix.sync.aligned.m8n8.x2.shared.b16 {%0,%1}, [%2];"
                 : "=r"(r0), "=r"(r1) : "r"(a));
}
__device__ __forceinline__ void mma16816(float* c, uint32_t a0, uint32_t a1, uint32_t a2, uint32_t a3,
                                         uint32_t b0, uint32_t b1){
    asm volatile("mma.sync.aligned.m16n8k16.row.col.f32.f16.f16.f32 "
                 "{%0,%1,%2,%3}, {%4,%5,%6,%7}, {%8,%9}, {%0,%1,%2,%3};"
                 : "+f"(c[0]), "+f"(c[1]), "+f"(c[2]), "+f"(c[3])
                 : "r"(a0), "r"(a1), "r"(a2), "r"(a3), "r"(b0), "r"(b1));
}

// ---------------------------------------------------------------------------
__global__ void xpre_kernel(const float* __restrict__ emb,
                            const float* __restrict__ Wf, const float* __restrict__ bf,
                            const float* __restrict__ Wi, const float* __restrict__ bi,
                            const float* __restrict__ Wo, const float* __restrict__ bo,
                            const float* __restrict__ Wc, const float* __restrict__ bc) {
    int v = blockIdx.x;
    __shared__ float e[EE];
    if (threadIdx.x < EE) e[threadIdx.x] = emb[v * EE + threadIdx.x];
    __syncthreads();
    for (int n = threadIdx.x; n < HH * 4; n += blockDim.x) {
        int j = n >> 2, gate = n & 3;
        const float* W = (gate==0)?Wf:(gate==1)?Wi:(gate==2)?Wo:Wc;
        const float* b = (gate==0)?bf:(gate==1)?bi:(gate==2)?bo:bc;
        float s = b[j];
#pragma unroll
        for (int k = 0; k < EE; k++) s = fmaf(e[k], W[k*HH+j], s);
        g_xpre[((size_t)v*HH + j)*4 + gate] = s;
    }
}

// ---------------------------------------------------------------------------
// Persistent HMMA LSTM: CTA = 32 batches, 511 steps.
// Warps 0-9: D[32,400] = [h_hi|h_lo](fp16) @ W^T(fp16), B frag loaded ONCE
// per (kc,tile) and reused by hi+lo MMAs. Epilogue: 400 threads, HW tanh.
// ---------------------------------------------------------------------------
__global__ void __launch_bounds__(NTH, 1)
lstm_kernel(const int* __restrict__ data32,
            const float* __restrict__ Wf, const float* __restrict__ Wi,
            const float* __restrict__ Wo4, const float* __restrict__ Wc,
            const float* __restrict__ WoOut, const float* __restrict__ boOut,
            float* __restrict__ out) {
    extern __shared__ char smem[];
    const uint32_t sbase = smem_u32(smem);
    const int tid = threadIdx.x, wid = tid >> 5, lane = tid & 31;
    const int b0 = blockIdx.x * BB;

    int*   toks = (int*)(smem + SM_TOKS);
    int*   ltok = (int*)(smem + SM_LTOK);
    int*   flag = (int*)(smem + SM_FLAG);
    float* gs   = (float*)(smem + SM_GS);

    if (tid == 0) {
        int is64 = 1;
        for (int i = 0; i < 64; i++) if (data32[2*i+1] != 0) { is64 = 0; break; }
        flag[0] = is64;
    }
    for (int idx = tid*4; idx < SM_GS - SM_W; idx += NTH*4)
        *(uint32_t*)(smem + SM_W + idx) = 0u;
    __syncthreads();
    for (int idx = tid; idx < 400 * HH; idx += NTH) {
        int n = idx / HH, k = idx % HH, gate = n / HH, j = n % HH;
        const float* W = (gate==0)?Wf:(gate==1)?Wi:(gate==2)?Wo4:Wc;
        *(__half*)(smem + SM_W + n*240 + k*2) = __float2half_rn(W[(EE+k)*HH + j]);
    }
    const int is64 = flag[0];
    if (tid < BB) {
        long long base = (long long)(b0 + tid) * TT;
        ltok[tid] = is64 ? data32[2*(base+TT-1)] : data32[base+TT-1];
        toks[tid] = is64 ? data32[2*base]        : data32[base];
    }
    __syncthreads();

    const int bg = (tid < 400) ? tid / 100 : 0;
    const int j  = (tid < 400) ? tid % 100 : 0;
    float c[8], hreg[8];
#pragma unroll
    for (int i = 0; i < 8; i++) { c[i] = 0.f; hreg[i] = 0.f; }

    const int m0  = (wid < 5) ? 0 : 16;
    const int nt0 = (wid % 5) * 10;
    const uint32_t aOff = (uint32_t)(m0 + (lane & 15)) * 240u + (uint32_t)(lane >> 4) * 16u;
    const uint32_t bAdr = sbase + SM_W + (uint32_t)(nt0*8 + (lane & 7)) * 240u
                        + (uint32_t)((lane >> 3) & 1) * 16u;

    int cur = 0;
    for (int t = 0; t < TT - 1; ++t) {
        __syncthreads();   // B1: h hi/lo staging + toks[cur] ready

        int tk[8]; float4 xp[8];
        if (tid < 400) {
#pragma unroll
            for (int i = 0; i < 8; i++) {
                tk[i] = toks[cur * BB + bg*8 + i];
                xp[i] = __ldg((const float4*)(g_xpre + ((size_t)tk[i]*HH + j)*4));
            }
        }
        if (wid == 12 && lane < BB) {
            long long base = (long long)(b0 + lane) * TT + (t + 1);
            toks[(cur ^ 1) * BB + lane] = is64 ? data32[2*base] : data32[base];
        }

        if (wid < 10) {
            float acc[10][4];
#pragma unroll
            for (int i = 0; i < 10; i++) { acc[i][0]=0.f; acc[i][1]=0.f; acc[i][2]=0.f; acc[i][3]=0.f; }
            uint32_t aH = sbase + SM_AH + aOff;
            uint32_t aL = sbase + SM_AL + aOff;
#pragma unroll
            for (int kc = 0; kc < 7; kc++) {
                uint32_t h0,h1,h2,h3, l0,l1,l2,l3;
                ldsm_x4(h0,h1,h2,h3, aH + kc*32);
                ldsm_x4(l0,l1,l2,l3, aL + kc*32);
#pragma unroll
                for (int i = 0; i < 10; i++) {
                    uint32_t b0r,b1r;
                    ldsm_x2(b0r,b1r, bAdr + i*(8*240) + kc*32);   // one B load, two MMAs
                    mma16816(acc[i], h0,h1,h2,h3, b0r,b1r);
                    mma16816(acc[i], l0,l1,l2,l3, b0r,b1r);
                }
            }
            int r0 = m0 + (lane >> 2), cl = (lane & 3) * 2;
#pragma unroll
            for (int i = 0; i < 10; i++) {
                int n = (nt0 + i)*8 + cl;
                *(float2*)(gs + r0*GSTR + n)     = make_float2(acc[i][0], acc[i][1]);
                *(float2*)(gs + (r0+8)*GSTR + n) = make_float2(acc[i][2], acc[i][3]);
            }
        }
        __syncthreads();   // B2: gs ready

        if (tid < 400) {
#pragma unroll
            for (int i = 0; i < 8; i++) {
                int b = bg*8 + i;
                float f  = fsigm_hw(gs[b*GSTR +       j] + xp[i].x);
                float ii = fsigm_hw(gs[b*GSTR + 100 + j] + xp[i].y);
                float o  = fsigm_hw(gs[b*GSTR + 200 + j] + xp[i].z);
                float gg = ftanh_hw(gs[b*GSTR + 300 + j] + xp[i].w);
                float cn = fmaf(c[i], f, ii * gg);
                bool  m  = (tk[i] != ltok[b]);
                c[i]    = m ? cn : c[i];
                hreg[i] = m ? o * ftanh_hw(cn) : hreg[i];
                __half hi = __float2half_rn(hreg[i]);
                __half lo = __float2half_rn(hreg[i] - __half2float(hi));
                *(__half*)(smem + SM_AH + b*240 + j*2) = hi;
                *(__half*)(smem + SM_AL + b*240 + j*2) = lo;
            }
        }
        cur ^= 1;
    }

    // output head (exact fp32 sigmoid)
    __syncthreads();
    if (tid < 400) {
#pragma unroll
        for (int i = 0; i < 8; i++) gs[(bg*8 + i)*104 + j] = hreg[i];
    }
    __syncthreads();
    if (tid < BB) {
        float z = boOut[0];
#pragma unroll 4
        for (int k = 0; k < HH; k++) z = fmaf(gs[tid*104 + k], WoOut[k], z);
        out[b0 + tid] = fsigm_x(z);
    }
}

// ---------------------------------------------------------------------------
extern "C" void kernel_launch(void* const* d_in, const int* in_sizes, int n_in,
                              void* d_out, int out_size) {
    const int*   data = (const int*)  d_in[0];
    const float* emb  = (const float*)d_in[1];
    const float* Wfh  = (const float*)d_in[2];
    const float* bfh  = (const float*)d_in[3];
    const float* Wih  = (const float*)d_in[4];
    const float* bih  = (const float*)d_in[5];
    const float* Woh  = (const float*)d_in[6];
    const float* boh  = (const float*)d_in[7];
    const float* Wch  = (const float*)d_in[8];
    const float* bch  = (const float*)d_in[9];
    const float* Wo   = (const float*)d_in[10];
    const float* bo   = (const float*)d_in[11];
    float* out = (float*)d_out;

    xpre_kernel<<<VOCAB, 128>>>(emb, Wfh, bfh, Wih, bih, Woh, boh, Wch, bch);

    cudaFuncSetAttribute(lstm_kernel, cudaFuncAttributeMaxDynamicSharedMemorySize, SM_END);
    lstm_kernel<<<NBLK, NTH, SM_END>>>(data, Wfh, Wih, Woh, Wch, Wo, bo, out);
}